// round 16
// baseline (speedup 1.0000x reference)
#include <cuda_runtime.h>
#include <math.h>

// Problem constants (fixed shapes from reference)
#define Bq   4
#define Nq   2048
#define DIN  128
#define Hq   4
#define HD   32
#define Kq   204          // int(0.1 * 2048)
#define KPAD 224          // padded K (multiple of 32)
#define KSTR 228          // smem row stride (conflict-free float4: gcd(57,32)=1)
#define BH   (Bq*Hq)      // 16

#define CP_ASYNC4(dst_u32, src_ptr) \
    asm volatile("cp.async.ca.shared.global [%0], [%1], 4;" \
                 :: "r"(dst_u32), "l"(src_ptr))
#define CP_COMMIT()  asm volatile("cp.async.commit_group;" ::: "memory")
#define CP_WAIT0()   asm volatile("cp.async.wait_group 0;" ::: "memory")

// Scratch (device globals)
__device__ float g_Wh[BH*Nq*HD];          // [bh][n][d]  4 MB
__device__ float g_si[BH*Nq];
__device__ float g_sj[BH*Nq];
__device__ int   g_sel[BH*Kq];            // selected neighbor cols, ascending
__device__ float g_selv[BH*KPAD];         // s_j at selected (+ -3e38 pads)
__device__ float g_sjmax[BH];
__device__ float g_WhSelT[BH*HD*KPAD];    // gathered Wh, transposed [d][k], pads 0

// ---------------------------------------------------------------------------
// Kernel 1: Wh = h @ W (per head) + s_i, s_j epilogue.   (r13 version)
// CTA: 32 rows, 128 threads = 4 warps. Warp w: rows w*8..w*8+7.
// ---------------------------------------------------------------------------
__global__ void __launch_bounds__(128) k1_wh(const float* __restrict__ h,
                                             const float* __restrict__ W,
                                             const float* __restrict__ a)
{
    __shared__ float hs[32][DIN];     // 16 KB
    __shared__ float Ws[32][DIN];     // 16 KB  [f-local][h*32+d]
    const int tid  = threadIdx.x;
    const int w    = tid >> 5;
    const int lane = tid & 31;
    const int hh   = lane >> 3;          // head
    const int dq   = lane & 7;           // d-quad
    const int row0 = blockIdx.x * 32;

    {
        const float4* src = (const float4*)(h + (size_t)row0 * DIN);
        #pragma unroll
        for (int i = 0; i < 8; ++i)
            ((float4*)hs)[tid + i * 128] = src[tid + i * 128];
    }

    float acc[8][4];
    #pragma unroll
    for (int r = 0; r < 8; ++r)
        #pragma unroll
        for (int j = 0; j < 4; ++j) acc[r][j] = 0.f;

    for (int c = 0; c < 4; ++c) {           // 4 chunks of 32 f
        const int f0 = c * 32;
        __syncthreads();
        #pragma unroll
        for (int i = 0; i < 8; ++i) {
            const int lin = tid + i * 128;
            const int hW  = lin >> 8;            // 256 float4 per head
            const int rem = lin & 255;
            const int f   = rem >> 3;
            const int dqq = rem & 7;
            *(float4*)&Ws[f][hW * 32 + dqq * 4] =
                *(const float4*)(W + hW * (DIN*HD) + (f0 + f) * HD + dqq * 4);
        }
        __syncthreads();

        #pragma unroll
        for (int f4 = 0; f4 < 32; f4 += 4) {
            float4 hv[8];
            #pragma unroll
            for (int r = 0; r < 8; ++r)
                hv[r] = *(const float4*)&hs[w * 8 + r][f0 + f4];   // broadcast
            #pragma unroll
            for (int u = 0; u < 4; ++u) {
                const float4 wv = *(const float4*)&Ws[f4 + u][hh * 32 + dq * 4];
                #pragma unroll
                for (int r = 0; r < 8; ++r) {
                    const float hvu = ((const float*)&hv[r])[u];
                    acc[r][0] += hvu * wv.x;
                    acc[r][1] += hvu * wv.y;
                    acc[r][2] += hvu * wv.z;
                    acc[r][3] += hvu * wv.w;
                }
            }
        }
    }

    const int b  = row0 >> 11;
    const int n0 = row0 & 2047;
    const int bh = b * Hq + hh;
    const float4 aiv = *(const float4*)(a + hh * 64 + dq * 4);
    const float4 ajv = *(const float4*)(a + hh * 64 + 32 + dq * 4);

    #pragma unroll
    for (int r = 0; r < 8; ++r) {
        const int n = n0 + w * 8 + r;
        *(float4*)&g_Wh[((size_t)bh * Nq + n) * HD + dq * 4] =
            make_float4(acc[r][0], acc[r][1], acc[r][2], acc[r][3]);
        float ps = acc[r][0]*aiv.x + acc[r][1]*aiv.y + acc[r][2]*aiv.z + acc[r][3]*aiv.w;
        float pj = acc[r][0]*ajv.x + acc[r][1]*ajv.y + acc[r][2]*ajv.z + acc[r][3]*ajv.w;
        #pragma unroll
        for (int o = 4; o; o >>= 1) {
            ps += __shfl_xor_sync(0xffffffffu, ps, o);
            pj += __shfl_xor_sync(0xffffffffu, pj, o);
        }
        if (dq == 0) {
            g_si[bh * Nq + n] = ps;
            g_sj[bh * Nq + n] = pj;
        }
    }
}

// ---------------------------------------------------------------------------
// Kernel 2a: per (b,h) radix-select top-K of s_j.  (r15 version, 512 thr)
// ---------------------------------------------------------------------------
__device__ __forceinline__ int block_incscan512(int v, int* wsum)
{
    __syncthreads();
    const int lane = threadIdx.x & 31, w = threadIdx.x >> 5;
    int inc = v;
    #pragma unroll
    for (int o = 1; o < 32; o <<= 1) {
        const int t = __shfl_up_sync(0xffffffffu, inc, o);
        if (lane >= o) inc += t;
    }
    if (lane == 31) wsum[w] = inc;
    __syncthreads();
    if (threadIdx.x == 0) {
        int s = 0;
        #pragma unroll
        for (int i = 0; i < 16; ++i) { const int t = wsum[i]; wsum[i] = s; s += t; }
    }
    __syncthreads();
    return inc + wsum[w];
}

__device__ __forceinline__ int block_exscan512(int v, int* wsum)
{
    return block_incscan512(v, wsum) - v;
}

__global__ void __launch_bounds__(512) k2a_select()
{
    __shared__ unsigned uvals[Nq];          // 8 KB
    __shared__ float    fvals[Nq];          // 8 KB
    __shared__ int      hist[256];
    __shared__ int      wsum[16];
    __shared__ float    redf[16];
    __shared__ unsigned sh_pref;
    __shared__ int      sh_rem;

    const int bh  = blockIdx.x;
    const int tid = threadIdx.x;

    float mx = -3.4e38f;
    #pragma unroll
    for (int i = 0; i < 4; ++i) {
        const int j = tid + i * 512;
        const float v = g_sj[bh * Nq + j];
        fvals[j] = v;
        unsigned u = __float_as_uint(v);
        u = (u & 0x80000000u) ? ~u : (u | 0x80000000u);
        uvals[j] = u;
        mx = fmaxf(mx, v);
    }
    #pragma unroll
    for (int o = 16; o; o >>= 1) mx = fmaxf(mx, __shfl_down_sync(0xffffffffu, mx, o));
    if ((tid & 31) == 0) redf[tid >> 5] = mx;
    __syncthreads();
    if (tid == 0) {
        float m = redf[0];
        #pragma unroll
        for (int i = 1; i < 16; ++i) m = fmaxf(m, redf[i]);
        g_sjmax[bh] = m;
    }

    unsigned prefix = 0;
    int remaining = Kq;
    for (int pass = 0; pass < 4; ++pass) {
        const int shift = 24 - 8 * pass;
        const unsigned mask_hi = (pass == 0) ? 0u : (0xFFFFFFFFu << (shift + 8));
        if (tid < 256) hist[tid] = 0;
        __syncthreads();
        #pragma unroll
        for (int i = 0; i < 4; ++i) {
            const unsigned u = uvals[tid + i * 512];
            if ((u & mask_hi) == prefix)
                atomicAdd(&hist[(u >> shift) & 255], 1);
        }
        __syncthreads();
        const int x = (tid < 256) ? hist[255 - tid] : 0;
        const int incl = block_incscan512(x, wsum);
        if (tid < 256 && incl >= remaining && (incl - x) < remaining) {
            sh_pref = prefix | ((unsigned)(255 - tid) << shift);
            sh_rem  = remaining - (incl - x);
        }
        __syncthreads();
        prefix    = sh_pref;
        remaining = sh_rem;
        __syncthreads();
    }
    const unsigned tau = prefix;
    const int tneed    = remaining;

    const int j0 = tid * 4;
    unsigned uloc[4];
    int myeq = 0;
    #pragma unroll
    for (int e = 0; e < 4; ++e) {
        uloc[e] = uvals[j0 + e];
        if (uloc[e] == tau) myeq++;
    }
    const int eqbase = block_exscan512(myeq, wsum);

    int flags = 0, cnt = 0, eqr = eqbase;
    #pragma unroll
    for (int e = 0; e < 4; ++e) {
        bool s;
        if (uloc[e] > tau)        s = true;
        else if (uloc[e] == tau) { s = (eqr < tneed); eqr++; }
        else                      s = false;
        if (s) { flags |= (1 << e); cnt++; }
    }
    int pos = block_exscan512(cnt, wsum);
    #pragma unroll
    for (int e = 0; e < 4; ++e) {
        if (flags & (1 << e)) {
            g_sel [bh * Kq + pos]    = j0 + e;
            g_selv[bh * KPAD + pos]  = fvals[j0 + e];
            pos++;
        }
    }
    if (tid >= Kq && tid < KPAD) g_selv[bh * KPAD + tid] = -3.0e38f;
}

// ---------------------------------------------------------------------------
// Kernel 2b: gather Wh_sel + transpose to g_WhSelT[d][k].   (r13 version)
// ---------------------------------------------------------------------------
__global__ void __launch_bounds__(128) k2b_gather()
{
    __shared__ float tile[56][33];
    const int tid  = threadIdx.x;
    const int bh   = blockIdx.x >> 2;
    const int k0   = (blockIdx.x & 3) * 56;

    #pragma unroll
    for (int i = 0; i < 14; ++i) {
        const int idx = tid + i * 128;
        const int kk  = idx >> 5;            // 0..55
        const int d   = idx & 31;
        const int k   = k0 + kk;
        float v = 0.f;
        if (k < Kq) {
            const int col = g_sel[bh * Kq + k];
            v = g_Wh[((size_t)bh * Nq + col) * HD + d];
        }
        tile[kk][d] = v;
    }
    __syncthreads();

    #pragma unroll
    for (int i = 0; i < 14; ++i) {
        const int idx = tid + i * 128;
        const int d   = idx / 56;
        const int kk  = idx - d * 56;
        g_WhSelT[((size_t)bh * HD + d) * KPAD + k0 + kk] = tile[kk][d];
    }
}

// ---------------------------------------------------------------------------
// Kernel 3: main pass. Gather via cp.async (LDGSTS) directly into smem wts
// (no destination registers, no long-scoreboard stalls), then dense in-place
// exp/scale pass, then the proven r15 GEMM.
// CTA = (bh, 32-row tile), 256 threads = 8 warps, ~61 KB dyn smem (3 CTA/SM).
// ---------------------------------------------------------------------------
#define K3_WHS  0
#define K3_WTS  (HD*KSTR*4)                        // 29184
#define K3_SEL  (K3_WTS + 32*KSTR*4)               // 58368
#define K3_SELV (K3_SEL + KPAD*4)                  // 59264
#define K3_SI   (K3_SELV + KPAD*4)                 // 60160
#define K3_M    (K3_SI + 128)                      // 60288
#define K3_Z    (K3_M + 128)                       // 60416
#define K3_SMEM (K3_Z + 128)                       // 60544

__global__ void __launch_bounds__(256, 3) k3_main(const float* __restrict__ adj,
                                                  float* __restrict__ out)
{
    extern __shared__ __align__(16) char k3raw[];
    float* whs  = (float*)(k3raw + K3_WHS);     // [d][KSTR]
    float* wts  = (float*)(k3raw + K3_WTS);     // [r][KSTR]
    int*   selS = (int*)  (k3raw + K3_SEL);
    float* selv = (float*)(k3raw + K3_SELV);
    float* siS  = (float*)(k3raw + K3_SI);
    float* mS   = (float*)(k3raw + K3_M);
    float* zS   = (float*)(k3raw + K3_Z);
    float* red  = whs;                          // reused after GEMM

    const int tid  = threadIdx.x;
    const int lane = tid & 31;
    const int w    = tid >> 5;

    const int bh   = blockIdx.x >> 6;
    const int tile = blockIdx.x & 63;
    const int b    = bh >> 2;
    const int hh   = bh & 3;
    const int i0   = tile * 32;

    // stage whs[d][k] from transposed global (coalesced float4)
    {
        const float4* src = (const float4*)(g_WhSelT + (size_t)bh * HD * KPAD);
        #pragma unroll
        for (int i = 0; i < 7; ++i) {
            const int idx = tid + i * 256;        // 0..1791
            const int d   = idx / (KPAD/4);
            const int q   = idx - d * (KPAD/4);
            *(float4*)&whs[d * KSTR + q * 4] = src[idx];
        }
    }
    if (tid < KPAD) {
        selS[tid] = (tid < Kq) ? g_sel[bh * Kq + tid] : 0;
        selv[tid] = g_selv[bh * KPAD + tid];
    }
    if (tid < 32) {
        const float sjm = g_sjmax[bh];
        const float si  = g_si[bh * Nq + i0 + tid];
        siS[tid] = si;
        const float x = si + sjm;
        mS[tid] = (x >= 0.f) ? x : 0.2f * x;
    }
    // zero wts pad region (k in [Kq, KPAD)) so the in-place scale pass is exact
    {
        const int npad = 32 * (KPAD - Kq);          // 640
        for (int idx = tid; idx < npad; idx += 256) {
            const int r  = idx / (KPAD - Kq);
            const int kk = Kq + idx - r * (KPAD - Kq);
            wts[r * KSTR + kk] = 0.f;
        }
    }
    __syncthreads();

    // ---- gather via cp.async: warp covers rows {w, w+8, w+16, w+24} ----
    {
        int col[7];
        #pragma unroll
        for (int c = 0; c < 7; ++c) {
            const int k = c * 32 + lane;
            col[c] = selS[(k < Kq) ? k : 0];
        }
        const float* adjb = adj + (size_t)b * Nq * Nq;
        const unsigned wts_u32 = (unsigned)__cvta_generic_to_shared(wts);

        #pragma unroll
        for (int r = 0; r < 4; ++r) {
            const int row = w + r * 8;
            const float* arow = adjb + (size_t)(i0 + row) * Nq;
            const unsigned dbase = wts_u32 + (unsigned)(row * KSTR) * 4u;
            #pragma unroll
            for (int c = 0; c < 7; ++c) {
                const int k = c * 32 + lane;
                if (k < Kq)
                    CP_ASYNC4(dbase + (unsigned)k * 4u, arow + col[c]);
            }
        }
        CP_COMMIT();
        CP_WAIT0();
    }
    __syncthreads();

    // ---- dense exp/scale pass (in place): thread = (row, k-octant) ----
    {
        const int gr = tid >> 3;          // 0..31
        const int gk = tid & 7;
        const float gsi = siS[gr];
        const float gm  = mS[gr];
        float* wrow = wts + gr * KSTR;
        float zl = 0.f;
        #pragma unroll
        for (int it = 0; it < 7; ++it) {
            const int q = it * 8 + gk;          // 0..55
            float4 wq = *(float4*)&wrow[q * 4];
            const float4 vj = *(const float4*)&selv[q * 4];
            float x, e, p;
            x = gsi + vj.x; e = (x >= 0.f) ? x : 0.2f*x; p = __expf(e - gm); zl += p; wq.x *= p;
            x = gsi + vj.y; e = (x >= 0.f) ? x : 0.2f*x; p = __expf(e - gm); zl += p; wq.y *= p;
            x = gsi + vj.z; e = (x >= 0.f) ? x : 0.2f*x; p = __expf(e - gm); zl += p; wq.z *= p;
            x = gsi + vj.w; e = (x >= 0.f) ? x : 0.2f*x; p = __expf(e - gm); zl += p; wq.w *= p;
            *(float4*)&wrow[q * 4] = wq;
        }
        zl += __shfl_xor_sync(0xffffffffu, zl, 1);
        zl += __shfl_xor_sync(0xffffffffu, zl, 2);
        zl += __shfl_xor_sync(0xffffffffu, zl, 4);
        if (gk == 0) zS[gr] = zl;
    }
    __syncthreads();

    // ---- GEMM: warp = (rowgroup w&3 -> 8 rows, k-half w>>2) ----
    const int rbase = (w & 3) * 8;
    const int kw    = w >> 2;
    const int kbase = kw * 112;

    float acc[8];
    #pragma unroll
    for (int r = 0; r < 8; ++r) acc[r] = 0.f;

    const float* whp = whs + lane * KSTR + kbase;
    #pragma unroll
    for (int k0 = 0; k0 < 112; k0 += 4) {
        const float4 whv = *(const float4*)&whp[k0];
        #pragma unroll
        for (int r = 0; r < 8; ++r) {
            const float4 g = *(const float4*)&wts[(rbase + r) * KSTR + kbase + k0];
            float s = acc[r];
            s += g.x * whv.x;
            s += g.y * whv.y;
            s += g.z * whv.z;
            s += g.w * whv.w;
            acc[r] = s;
        }
    }
    __syncthreads();

    // cross-k-half reduction through smem (reuse whs)
    if (kw == 1) {
        #pragma unroll
        for (int r = 0; r < 8; ++r)
            red[(rbase + r) * 32 + lane] = acc[r];
    }
    __syncthreads();
    if (kw == 0) {
        #pragma unroll
        for (int r = 0; r < 8; ++r) {
            const float tot  = acc[r] + red[(rbase + r) * 32 + lane];
            const float invz = 1.0f / zS[rbase + r];
            out[(size_t)(b * Nq + i0 + rbase + r) * (Hq * HD) + hh * HD + lane] = tot * invz;
        }
    }
}

// ---------------------------------------------------------------------------
extern "C" void kernel_launch(void* const* d_in, const int* in_sizes, int n_in,
                              void* d_out, int out_size)
{
    const float *h = nullptr, *adj = nullptr, *W = nullptr, *a = nullptr;
    for (int i = 0; i < n_in; ++i) {
        switch (in_sizes[i]) {
            case Bq*Nq*DIN:  h   = (const float*)d_in[i]; break;  // 1048576
            case Bq*Nq*Nq:   adj = (const float*)d_in[i]; break;  // 16777216
            case Hq*DIN*HD:  W   = (const float*)d_in[i]; break;  // 16384
            case Hq*2*HD:    a   = (const float*)d_in[i]; break;  // 256
            default: break;
        }
    }
    float* out = (float*)d_out;

    cudaFuncSetAttribute(k3_main, cudaFuncAttributeMaxDynamicSharedMemorySize, K3_SMEM);

    k1_wh     <<<(Bq*Nq)/32, 128>>>(h, W, a);
    k2a_select<<<BH, 512>>>();
    k2b_gather<<<BH * 4, 128>>>();
    k3_main   <<<BH * (Nq/32), 256, K3_SMEM>>>(adj, out);
}

// round 17
// speedup vs baseline: 1.1143x; 1.1143x over previous
#include <cuda_runtime.h>
#include <math.h>

// Problem constants (fixed shapes from reference)
#define Bq   4
#define Nq   2048
#define DIN  128
#define Hq   4
#define HD   32
#define Kq   204          // int(0.1 * 2048)
#define KPAD 224          // padded K (multiple of 32)
#define KSTR 228          // smem row stride (conflict-free float4: gcd(57,32)=1)
#define BH   (Bq*Hq)      // 16

#define CP_ASYNC16(dst_u32, src_ptr) \
    asm volatile("cp.async.cg.shared.global [%0], [%1], 16;" \
                 :: "r"(dst_u32), "l"(src_ptr))
#define CP_COMMIT()  asm volatile("cp.async.commit_group;" ::: "memory")
#define CP_WAIT0()   asm volatile("cp.async.wait_group 0;" ::: "memory")

// Scratch (device globals)
__device__ float g_Wh[BH*Nq*HD];          // [bh][n][d]  4 MB
__device__ float g_si[BH*Nq];
__device__ float g_sj[BH*Nq];
__device__ int   g_sel[BH*Kq];            // selected neighbor cols, ascending
__device__ float g_selv[BH*KPAD];         // s_j at selected (+ -3e38 pads)
__device__ float g_sjmax[BH];
__device__ float g_WhSelT[BH*HD*KPAD];    // gathered Wh, transposed [d][k], pads 0

// ---------------------------------------------------------------------------
// Kernel 1: Wh = h @ W (per head) + s_i, s_j epilogue.   (r13 version)
// CTA: 32 rows, 128 threads = 4 warps. Warp w: rows w*8..w*8+7.
// ---------------------------------------------------------------------------
__global__ void __launch_bounds__(128) k1_wh(const float* __restrict__ h,
                                             const float* __restrict__ W,
                                             const float* __restrict__ a)
{
    __shared__ float hs[32][DIN];     // 16 KB
    __shared__ float Ws[32][DIN];     // 16 KB  [f-local][h*32+d]
    const int tid  = threadIdx.x;
    const int w    = tid >> 5;
    const int lane = tid & 31;
    const int hh   = lane >> 3;          // head
    const int dq   = lane & 7;           // d-quad
    const int row0 = blockIdx.x * 32;

    {
        const float4* src = (const float4*)(h + (size_t)row0 * DIN);
        #pragma unroll
        for (int i = 0; i < 8; ++i)
            ((float4*)hs)[tid + i * 128] = src[tid + i * 128];
    }

    float acc[8][4];
    #pragma unroll
    for (int r = 0; r < 8; ++r)
        #pragma unroll
        for (int j = 0; j < 4; ++j) acc[r][j] = 0.f;

    for (int c = 0; c < 4; ++c) {           // 4 chunks of 32 f
        const int f0 = c * 32;
        __syncthreads();
        #pragma unroll
        for (int i = 0; i < 8; ++i) {
            const int lin = tid + i * 128;
            const int hW  = lin >> 8;            // 256 float4 per head
            const int rem = lin & 255;
            const int f   = rem >> 3;
            const int dqq = rem & 7;
            *(float4*)&Ws[f][hW * 32 + dqq * 4] =
                *(const float4*)(W + hW * (DIN*HD) + (f0 + f) * HD + dqq * 4);
        }
        __syncthreads();

        #pragma unroll
        for (int f4 = 0; f4 < 32; f4 += 4) {
            float4 hv[8];
            #pragma unroll
            for (int r = 0; r < 8; ++r)
                hv[r] = *(const float4*)&hs[w * 8 + r][f0 + f4];   // broadcast
            #pragma unroll
            for (int u = 0; u < 4; ++u) {
                const float4 wv = *(const float4*)&Ws[f4 + u][hh * 32 + dq * 4];
                #pragma unroll
                for (int r = 0; r < 8; ++r) {
                    const float hvu = ((const float*)&hv[r])[u];
                    acc[r][0] += hvu * wv.x;
                    acc[r][1] += hvu * wv.y;
                    acc[r][2] += hvu * wv.z;
                    acc[r][3] += hvu * wv.w;
                }
            }
        }
    }

    const int b  = row0 >> 11;
    const int n0 = row0 & 2047;
    const int bh = b * Hq + hh;
    const float4 aiv = *(const float4*)(a + hh * 64 + dq * 4);
    const float4 ajv = *(const float4*)(a + hh * 64 + 32 + dq * 4);

    #pragma unroll
    for (int r = 0; r < 8; ++r) {
        const int n = n0 + w * 8 + r;
        *(float4*)&g_Wh[((size_t)bh * Nq + n) * HD + dq * 4] =
            make_float4(acc[r][0], acc[r][1], acc[r][2], acc[r][3]);
        float ps = acc[r][0]*aiv.x + acc[r][1]*aiv.y + acc[r][2]*aiv.z + acc[r][3]*aiv.w;
        float pj = acc[r][0]*ajv.x + acc[r][1]*ajv.y + acc[r][2]*ajv.z + acc[r][3]*ajv.w;
        #pragma unroll
        for (int o = 4; o; o >>= 1) {
            ps += __shfl_xor_sync(0xffffffffu, ps, o);
            pj += __shfl_xor_sync(0xffffffffu, pj, o);
        }
        if (dq == 0) {
            g_si[bh * Nq + n] = ps;
            g_sj[bh * Nq + n] = pj;
        }
    }
}

// ---------------------------------------------------------------------------
// Kernel 2a: per (b,h) radix-select top-K of s_j.  (r15 version, 512 thr)
// ---------------------------------------------------------------------------
__device__ __forceinline__ int block_incscan512(int v, int* wsum)
{
    __syncthreads();
    const int lane = threadIdx.x & 31, w = threadIdx.x >> 5;
    int inc = v;
    #pragma unroll
    for (int o = 1; o < 32; o <<= 1) {
        const int t = __shfl_up_sync(0xffffffffu, inc, o);
        if (lane >= o) inc += t;
    }
    if (lane == 31) wsum[w] = inc;
    __syncthreads();
    if (threadIdx.x == 0) {
        int s = 0;
        #pragma unroll
        for (int i = 0; i < 16; ++i) { const int t = wsum[i]; wsum[i] = s; s += t; }
    }
    __syncthreads();
    return inc + wsum[w];
}

__device__ __forceinline__ int block_exscan512(int v, int* wsum)
{
    return block_incscan512(v, wsum) - v;
}

__global__ void __launch_bounds__(512) k2a_select()
{
    __shared__ unsigned uvals[Nq];          // 8 KB
    __shared__ float    fvals[Nq];          // 8 KB
    __shared__ int      hist[256];
    __shared__ int      wsum[16];
    __shared__ float    redf[16];
    __shared__ unsigned sh_pref;
    __shared__ int      sh_rem;

    const int bh  = blockIdx.x;
    const int tid = threadIdx.x;

    float mx = -3.4e38f;
    #pragma unroll
    for (int i = 0; i < 4; ++i) {
        const int j = tid + i * 512;
        const float v = g_sj[bh * Nq + j];
        fvals[j] = v;
        unsigned u = __float_as_uint(v);
        u = (u & 0x80000000u) ? ~u : (u | 0x80000000u);
        uvals[j] = u;
        mx = fmaxf(mx, v);
    }
    #pragma unroll
    for (int o = 16; o; o >>= 1) mx = fmaxf(mx, __shfl_down_sync(0xffffffffu, mx, o));
    if ((tid & 31) == 0) redf[tid >> 5] = mx;
    __syncthreads();
    if (tid == 0) {
        float m = redf[0];
        #pragma unroll
        for (int i = 1; i < 16; ++i) m = fmaxf(m, redf[i]);
        g_sjmax[bh] = m;
    }

    unsigned prefix = 0;
    int remaining = Kq;
    for (int pass = 0; pass < 4; ++pass) {
        const int shift = 24 - 8 * pass;
        const unsigned mask_hi = (pass == 0) ? 0u : (0xFFFFFFFFu << (shift + 8));
        if (tid < 256) hist[tid] = 0;
        __syncthreads();
        #pragma unroll
        for (int i = 0; i < 4; ++i) {
            const unsigned u = uvals[tid + i * 512];
            if ((u & mask_hi) == prefix)
                atomicAdd(&hist[(u >> shift) & 255], 1);
        }
        __syncthreads();
        const int x = (tid < 256) ? hist[255 - tid] : 0;
        const int incl = block_incscan512(x, wsum);
        if (tid < 256 && incl >= remaining && (incl - x) < remaining) {
            sh_pref = prefix | ((unsigned)(255 - tid) << shift);
            sh_rem  = remaining - (incl - x);
        }
        __syncthreads();
        prefix    = sh_pref;
        remaining = sh_rem;
        __syncthreads();
    }
    const unsigned tau = prefix;
    const int tneed    = remaining;

    const int j0 = tid * 4;
    unsigned uloc[4];
    int myeq = 0;
    #pragma unroll
    for (int e = 0; e < 4; ++e) {
        uloc[e] = uvals[j0 + e];
        if (uloc[e] == tau) myeq++;
    }
    const int eqbase = block_exscan512(myeq, wsum);

    int flags = 0, cnt = 0, eqr = eqbase;
    #pragma unroll
    for (int e = 0; e < 4; ++e) {
        bool s;
        if (uloc[e] > tau)        s = true;
        else if (uloc[e] == tau) { s = (eqr < tneed); eqr++; }
        else                      s = false;
        if (s) { flags |= (1 << e); cnt++; }
    }
    int pos = block_exscan512(cnt, wsum);
    #pragma unroll
    for (int e = 0; e < 4; ++e) {
        if (flags & (1 << e)) {
            g_sel [bh * Kq + pos]    = j0 + e;
            g_selv[bh * KPAD + pos]  = fvals[j0 + e];
            pos++;
        }
    }
    if (tid >= Kq && tid < KPAD) g_selv[bh * KPAD + tid] = -3.0e38f;
}

// ---------------------------------------------------------------------------
// Kernel 2b: gather Wh_sel + transpose to g_WhSelT[d][k].
// CTA = (bh, k-segment of 28), 128 threads, 128 CTAs (fills more SMs).
// ---------------------------------------------------------------------------
__global__ void __launch_bounds__(128) k2b_gather()
{
    __shared__ float tile[28][33];
    const int tid  = threadIdx.x;
    const int bh   = blockIdx.x >> 3;
    const int k0   = (blockIdx.x & 7) * 28;

    #pragma unroll
    for (int i = 0; i < 7; ++i) {
        const int idx = tid + i * 128;
        const int kk  = idx >> 5;            // 0..27
        const int d   = idx & 31;
        const int k   = k0 + kk;
        float v = 0.f;
        if (k < Kq) {
            const int col = g_sel[bh * Kq + k];
            v = g_Wh[((size_t)bh * Nq + col) * HD + d];
        }
        tile[kk][d] = v;
    }
    __syncthreads();

    #pragma unroll
    for (int i = 0; i < 7; ++i) {
        const int idx = tid + i * 128;
        const int d   = idx / 28;
        const int kk  = idx - d * 28;
        g_WhSelT[((size_t)bh * HD + d) * KPAD + k0 + kk] = tile[kk][d];
    }
}

// ---------------------------------------------------------------------------
// Kernel 3: main pass, direct sorted gather from adj.  (r15 structure)
// whs staged via cp.async (coalesced 16B), waited only AFTER gather+exp ->
// staging L2 latency overlaps the gather phase.
// CTA = (bh, 32-row tile), 256 threads = 8 warps, ~61 KB dyn smem (3 CTA/SM).
// ---------------------------------------------------------------------------
#define K3_WHS  0
#define K3_WTS  (HD*KSTR*4)                        // 29184
#define K3_SEL  (K3_WTS + 32*KSTR*4)               // 58368
#define K3_SELV (K3_SEL + KPAD*4)                  // 59264
#define K3_SI   (K3_SELV + KPAD*4)                 // 60160
#define K3_M    (K3_SI + 128)                      // 60288
#define K3_Z    (K3_M + 128)                       // 60416
#define K3_SMEM (K3_Z + 128)                       // 60544

__global__ void __launch_bounds__(256, 3) k3_main(const float* __restrict__ adj,
                                                  float* __restrict__ out)
{
    extern __shared__ __align__(16) char k3raw[];
    float* whs  = (float*)(k3raw + K3_WHS);     // [d][KSTR]
    float* wts  = (float*)(k3raw + K3_WTS);     // [r][KSTR]
    int*   selS = (int*)  (k3raw + K3_SEL);
    float* selv = (float*)(k3raw + K3_SELV);
    float* siS  = (float*)(k3raw + K3_SI);
    float* mS   = (float*)(k3raw + K3_M);
    float* zS   = (float*)(k3raw + K3_Z);
    float* red  = whs;                          // reused after GEMM

    const int tid  = threadIdx.x;
    const int lane = tid & 31;
    const int w    = tid >> 5;

    const int bh   = blockIdx.x >> 6;
    const int tile = blockIdx.x & 63;
    const int b    = bh >> 2;
    const int hh   = bh & 3;
    const int i0   = tile * 32;

    // stage whs[d][k] via cp.async (coalesced 16B); waited after gather phase
    {
        const float4* src = (const float4*)(g_WhSelT + (size_t)bh * HD * KPAD);
        const unsigned whs_u32 = (unsigned)__cvta_generic_to_shared(whs);
        #pragma unroll
        for (int i = 0; i < 7; ++i) {
            const int idx = tid + i * 256;        // 0..1791
            const int d   = idx / (KPAD/4);
            const int q   = idx - d * (KPAD/4);
            CP_ASYNC16(whs_u32 + (unsigned)(d * KSTR + q * 4) * 4u, src + idx);
        }
        CP_COMMIT();
    }
    if (tid < KPAD) {
        selS[tid] = (tid < Kq) ? g_sel[bh * Kq + tid] : 0;
        selv[tid] = g_selv[bh * KPAD + tid];
    }
    if (tid < 32) {
        const float sjm = g_sjmax[bh];
        const float si  = g_si[bh * Nq + i0 + tid];
        siS[tid] = si;
        const float x = si + sjm;
        mS[tid] = (x >= 0.f) ? x : 0.2f * x;
    }
    __syncthreads();

    // ---- gather + weights: warp covers rows {w, w+8, w+16, w+24} ----
    {
        int   col[7];
        float vj [7];
        #pragma unroll
        for (int c = 0; c < 7; ++c) {
            const int k = c * 32 + lane;
            col[c] = selS[k];
            vj [c] = selv[k];
        }
        const float* adjb = adj + (size_t)b * Nq * Nq;

        #pragma unroll
        for (int half = 0; half < 2; ++half) {
            const int ra = w + half * 16;
            const int rb = ra + 8;
            const float* rowA = adjb + (size_t)(i0 + ra) * Nq;
            const float* rowB = adjb + (size_t)(i0 + rb) * Nq;

            float ava[7], avb[7];
            #pragma unroll
            for (int c = 0; c < 7; ++c) ava[c] = __ldg(&rowA[col[c]]);
            #pragma unroll
            for (int c = 0; c < 7; ++c) avb[c] = __ldg(&rowB[col[c]]);

            // row A
            {
                const float gsi = siS[ra], gm = mS[ra];
                float zl = 0.f;
                #pragma unroll
                for (int c = 0; c < 7; ++c) {
                    const float x = gsi + vj[c];
                    const float e = (x >= 0.f) ? x : 0.2f * x;
                    const float p = __expf(e - gm);
                    zl += p;
                    wts[ra * KSTR + c * 32 + lane] = p * ava[c];
                }
                #pragma unroll
                for (int o = 16; o; o >>= 1)
                    zl += __shfl_xor_sync(0xffffffffu, zl, o);
                if (lane == 0) zS[ra] = zl;
            }
            // row B
            {
                const float gsi = siS[rb], gm = mS[rb];
                float zl = 0.f;
                #pragma unroll
                for (int c = 0; c < 7; ++c) {
                    const float x = gsi + vj[c];
                    const float e = (x >= 0.f) ? x : 0.2f * x;
                    const float p = __expf(e - gm);
                    zl += p;
                    wts[rb * KSTR + c * 32 + lane] = p * avb[c];
                }
                #pragma unroll
                for (int o = 16; o; o >>= 1)
                    zl += __shfl_xor_sync(0xffffffffu, zl, o);
                if (lane == 0) zS[rb] = zl;
            }
        }
    }
    CP_WAIT0();          // whs ready (fetched during the gather phase)
    __syncthreads();

    // ---- GEMM: warp = (rowgroup w&3 -> 8 rows, k-half w>>2) ----
    const int rbase = (w & 3) * 8;
    const int kw    = w >> 2;
    const int kbase = kw * 112;

    float acc[8];
    #pragma unroll
    for (int r = 0; r < 8; ++r) acc[r] = 0.f;

    const float* whp = whs + lane * KSTR + kbase;
    #pragma unroll
    for (int k0 = 0; k0 < 112; k0 += 4) {
        const float4 whv = *(const float4*)&whp[k0];
        #pragma unroll
        for (int r = 0; r < 8; ++r) {
            const float4 g = *(const float4*)&wts[(rbase + r) * KSTR + kbase + k0];
            float s = acc[r];
            s += g.x * whv.x;
            s += g.y * whv.y;
            s += g.z * whv.z;
            s += g.w * whv.w;
            acc[r] = s;
        }
    }
    __syncthreads();

    // cross-k-half reduction through smem (reuse whs)
    if (kw == 1) {
        #pragma unroll
        for (int r = 0; r < 8; ++r)
            red[(rbase + r) * 32 + lane] = acc[r];
    }
    __syncthreads();
    if (kw == 0) {
        #pragma unroll
        for (int r = 0; r < 8; ++r) {
            const float tot  = acc[r] + red[(rbase + r) * 32 + lane];
            const float invz = 1.0f / zS[rbase + r];
            out[(size_t)(b * Nq + i0 + rbase + r) * (Hq * HD) + hh * HD + lane] = tot * invz;
        }
    }
}

// ---------------------------------------------------------------------------
extern "C" void kernel_launch(void* const* d_in, const int* in_sizes, int n_in,
                              void* d_out, int out_size)
{
    const float *h = nullptr, *adj = nullptr, *W = nullptr, *a = nullptr;
    for (int i = 0; i < n_in; ++i) {
        switch (in_sizes[i]) {
            case Bq*Nq*DIN:  h   = (const float*)d_in[i]; break;  // 1048576
            case Bq*Nq*Nq:   adj = (const float*)d_in[i]; break;  // 16777216
            case Hq*DIN*HD:  W   = (const float*)d_in[i]; break;  // 16384
            case Hq*2*HD:    a   = (const float*)d_in[i]; break;  // 256
            default: break;
        }
    }
    float* out = (float*)d_out;

    cudaFuncSetAttribute(k3_main, cudaFuncAttributeMaxDynamicSharedMemorySize, K3_SMEM);

    k1_wh     <<<(Bq*Nq)/32, 128>>>(h, W, a);
    k2a_select<<<BH, 512>>>();
    k2b_gather<<<BH * 8, 128>>>();
    k3_main   <<<BH * (Nq/32), 256, K3_SMEM>>>(adj, out);
}